// round 5
// baseline (speedup 1.0000x reference)
#include <cuda_runtime.h>

#define B_    8
#define N_    1024
#define H_    4
#define NEG   0.2f
#define BH_   32

// Scratch (__device__ globals; no allocation allowed)
__device__ float          gH[B_ * N_ * 128];        // projected features (4 MB)
__device__ float          gE1[BH_ * N_], gE2[BH_ * N_];   // exps, sorted order
__device__ unsigned short gPerm[BH_ * N_];
__device__ float          gTot[BH_ * 32 * 2 * 32];  // per-seg vector totals
__device__ int            gBkt[BH_ * 1026];         // bucket start offsets
__device__ float          gQC1[BH_ * N_], gQC2[BH_ * N_]; // per-query coeffs (bucket order)
__device__ unsigned short gQOut[BH_ * N_];          // original query index (bucket order)

// ---------------------------------------------------------------------------
// Kernel 1: h = x @ W   (8192x128 @ 128x128, fp32). 64x64 tile, 4x4/thread.
// ---------------------------------------------------------------------------
__global__ __launch_bounds__(256) void gemm_kernel(const float* __restrict__ A,
                                                   const float* __restrict__ W) {
    __shared__ float As[16][64];
    __shared__ float Bs[16][64];
    const int bm = blockIdx.x * 64, bn = blockIdx.y * 64;
    const int tid = threadIdx.x, tr = tid >> 4, tc = tid & 15;

    float acc[4][4];
#pragma unroll
    for (int i = 0; i < 4; i++)
#pragma unroll
        for (int j = 0; j < 4; j++) acc[i][j] = 0.f;

    for (int k0 = 0; k0 < 128; k0 += 16) {
#pragma unroll 4
        for (int i = tid; i < 1024; i += 256) {
            int m = i >> 4, kk = i & 15;
            As[kk][m] = A[(bm + m) * 128 + k0 + kk];
        }
#pragma unroll 4
        for (int i = tid; i < 1024; i += 256) {
            int kk = i >> 6, n = i & 63;
            Bs[kk][n] = W[(k0 + kk) * 128 + bn + n];
        }
        __syncthreads();
#pragma unroll
        for (int kk = 0; kk < 16; kk++) {
            float a[4], b[4];
#pragma unroll
            for (int i = 0; i < 4; i++) a[i] = As[kk][tr * 4 + i];
#pragma unroll
            for (int j = 0; j < 4; j++) b[j] = Bs[kk][tc * 4 + j];
#pragma unroll
            for (int i = 0; i < 4; i++)
#pragma unroll
                for (int j = 0; j < 4; j++) acc[i][j] = fmaf(a[i], b[j], acc[i][j]);
        }
        __syncthreads();
    }
#pragma unroll
    for (int i = 0; i < 4; i++)
        *reinterpret_cast<float4*>(&gH[(bm + tr * 4 + i) * 128 + bn + tc * 4]) =
            make_float4(acc[i][0], acc[i][1], acc[i][2], acc[i][3]);
}

// ---------------------------------------------------------------------------
// Kernel 2: prep. One block per (b,h), 1024 threads. Narrow but minimal.
// ---------------------------------------------------------------------------
struct PrepSmem {
    float          hL[1024 * 33];    // head slice, stride-33 (132 KB)
    float          dv[1024];
    float          e1[1024], e2[1024];
    float          pe1[1024], pe2[1024];
    float          wsum[32];
    int            wsumI[32];
    float          asr[32], ads[32];
    unsigned short pm[1024];
    int            cnt[1025];
    int            starts[1026];
};

__device__ __forceinline__ void shfl_pass(float& v, int& idx, int j, int k, int tid) {
    float pv = __shfl_xor_sync(0xFFFFFFFFu, v, j);
    int   pi = __shfl_xor_sync(0xFFFFFFFFu, idx, j);
    bool  up   = ((tid & k) == 0);
    bool  iLow = ((tid & j) == 0);
    float lo = iLow ? v : pv, hi = iLow ? pv : v;
    bool  sw = up ? (lo > hi) : (lo < hi);
    if (sw) { v = pv; idx = pi; }
}

__global__ __launch_bounds__(1024) void prep_kernel(const float* __restrict__ a_src,
                                                    const float* __restrict__ a_dst) {
    extern __shared__ char smem_raw[];
    PrepSmem& S = *reinterpret_cast<PrepSmem*>(smem_raw);

    const int bh = blockIdx.x, b = bh >> 2, head = bh & 3;
    const int tid = threadIdx.x, lane = tid & 31, wid = tid >> 5;
    const float* hbase = gH + (size_t)(b * 1024) * 128 + head * 32;

    if (tid < 32) { S.asr[tid] = a_src[head * 32 + tid]; S.ads[tid] = a_dst[head * 32 + tid]; }

    // --- stage head slice (coalesced float4 reads) ---
    for (int g = tid; g < 8192; g += 1024) {
        int r = g >> 3, c4 = g & 7;
        float4 v = reinterpret_cast<const float4*>(hbase + (size_t)r * 128)[c4];
        int base = r * 33 + c4 * 4;
        S.hL[base + 0] = v.x; S.hL[base + 1] = v.y;
        S.hL[base + 2] = v.z; S.hL[base + 3] = v.w;
    }
    __syncthreads();

    // --- dots ---
    float v, s;
    {
        float accd = 0.f, accs = 0.f;
#pragma unroll
        for (int c = 0; c < 32; c++) {
            float hv = S.hL[tid * 33 + c];
            accd = fmaf(hv, S.ads[c], accd);
            accs = fmaf(hv, S.asr[c], accs);
        }
        v = accd; s = accs;
    }
    int idx = tid;

    // --- bitonic sort: k=2..32 in registers ---
#pragma unroll
    for (int k = 2; k <= 32; k <<= 1)
#pragma unroll
        for (int j = k >> 1; j >= 1; j >>= 1) shfl_pass(v, idx, j, k, tid);
    S.dv[tid] = v; S.pm[tid] = (unsigned short)idx;
    __syncthreads();

    // --- k=64..1024: cross-warp smem passes + shfl tails ---
    for (int k = 64; k <= 1024; k <<= 1) {
        for (int j = k >> 1; j >= 32; j >>= 1) {
            float          v0 = S.dv[tid];
            unsigned short i0 = S.pm[tid];
            float          pv = S.dv[tid ^ j];
            unsigned short pi = S.pm[tid ^ j];
            bool  up   = ((tid & k) == 0);
            bool  iLow = ((tid & j) == 0);
            float lo = iLow ? v0 : pv, hi = iLow ? pv : v0;
            bool  sw = up ? (lo > hi) : (lo < hi);
            __syncthreads();
            S.dv[tid] = sw ? pv : v0;
            S.pm[tid] = sw ? pi : i0;
            __syncthreads();
        }
        v = S.dv[tid]; idx = S.pm[tid];
#pragma unroll
        for (int j = 16; j >= 1; j >>= 1) shfl_pass(v, idx, j, k, tid);
        S.dv[tid] = v; S.pm[tid] = (unsigned short)idx;
        __syncthreads();
    }

    // --- exps (v == sorted d at tid) ---
    const float dmax = S.dv[1023];
    float x   = v - dmax;
    float e1v = __expf(x);
    float e2v = __expf(NEG * x);
    S.e1[tid] = e1v;
    S.e2[tid] = e2v;
    gE1[bh * 1024 + tid]   = e1v;
    gE2[bh * 1024 + tid]   = e2v;
    gPerm[bh * 1024 + tid] = S.pm[tid];

    // --- inclusive block scans of e1, e2 ---
#pragma unroll
    for (int f = 0; f < 2; f++) {
        float sv = f ? e2v : e1v;
#pragma unroll
        for (int off = 1; off < 32; off <<= 1) {
            float n = __shfl_up_sync(0xFFFFFFFFu, sv, off);
            if (lane >= off) sv += n;
        }
        if (lane == 31) S.wsum[wid] = sv;
        __syncthreads();
        if (wid == 0) {
            float w = S.wsum[lane];
#pragma unroll
            for (int off = 1; off < 32; off <<= 1) {
                float n = __shfl_up_sync(0xFFFFFFFFu, w, off);
                if (lane >= off) w += n;
            }
            S.wsum[lane] = w;
        }
        __syncthreads();
        (f ? S.pe2 : S.pe1)[tid] = sv + (wid ? S.wsum[wid - 1] : 0.f);
        __syncthreads();
    }

    // --- binary search + per-query coefficients ---
    float c1c, c2c;
    int   kk;
    {
        const float T1 = S.pe1[1023];
        float key = -s;
        int   k   = 0;
#pragma unroll
        for (int step = 1024; step >= 1; step >>= 1) {
            int nk = k + step;
            if (nk <= 1024 && S.dv[nk - 1] < key) k = nk;
        }
        kk = k;
        float u  = s + dmax;
        float m  = fmaxf(u, NEG * u);
        float w1 = __expf(u - m);
        float w2 = __expf(NEG * u - m);
        float P1 = (k > 0) ? S.pe1[k - 1] : 0.f;
        float P2 = (k > 0) ? S.pe2[k - 1] : 0.f;
        float den = fmaf(w1, T1 - P1, w2 * P2);
        float inv = 1.f / den;
        c1c = w1 * inv;
        c2c = w2 * inv;
    }

    // --- counting sort of queries by bucket = k (0..1024) ---
    for (int i = tid; i < 1025; i += 1024) S.cnt[i] = 0;
    __syncthreads();
    atomicAdd(&S.cnt[kk], 1);
    __syncthreads();
    {
        int cv = S.cnt[tid];
#pragma unroll
        for (int off = 1; off < 32; off <<= 1) {
            int n = __shfl_up_sync(0xFFFFFFFFu, cv, off);
            if (lane >= off) cv += n;
        }
        if (lane == 31) S.wsumI[wid] = cv;
        __syncthreads();
        if (wid == 0) {
            int w = S.wsumI[lane];
#pragma unroll
            for (int off = 1; off < 32; off <<= 1) {
                int n = __shfl_up_sync(0xFFFFFFFFu, w, off);
                if (lane >= off) w += n;
            }
            S.wsumI[lane] = w;
        }
        __syncthreads();
        S.starts[tid + 1] = cv + (wid ? S.wsumI[wid - 1] : 0);
        if (tid == 0) S.starts[0] = 0;
        __syncthreads();
        if (tid == 0) S.starts[1025] = S.starts[1024] + S.cnt[1024];
        __syncthreads();
    }
    for (int i = tid; i < 1025; i += 1024) S.cnt[i] = 0;
    __syncthreads();
    {
        int pos = S.starts[kk] + atomicAdd(&S.cnt[kk], 1);
        gQC1[bh * 1024 + pos]  = c1c;
        gQC2[bh * 1024 + pos]  = c2c;
        gQOut[bh * 1024 + pos] = (unsigned short)tid;
    }
    for (int i = tid; i < 1026; i += 1024) gBkt[bh * 1026 + i] = S.starts[i];

    // --- per-segment vector totals (warp = seg, lane = channel) ---
    {
        const int seg = wid, c = lane, j0 = seg * 32;
        float t1 = 0.f, t2 = 0.f;
#pragma unroll
        for (int jj = 0; jj < 32; jj++) {
            int   j  = j0 + jj;
            float hv = S.hL[S.pm[j] * 33 + c];
            t1 = fmaf(S.e1[j], hv, t1);
            t2 = fmaf(S.e2[j], hv, t2);
        }
        gTot[((bh * 32 + seg) * 2 + 0) * 32 + c] = t1;
        gTot[((bh * 32 + seg) * 2 + 1) * 32 + c] = t2;
    }
}

// ---------------------------------------------------------------------------
// Kernel 3: wide fused prefix + merge-emit queries.
// Grid (bh=32, sg=4), 256 threads. Warp = segment sg*8+wid of sorted j.
// ---------------------------------------------------------------------------
__global__ __launch_bounds__(256) void pvq_kernel(float* __restrict__ out) {
    __shared__ float          sE1[256], sE2[256];
    __shared__ int            sPerm[256];
    __shared__ int            sBkt[258];
    __shared__ float          sHr[256 * 32];
    __shared__ float          sC1[1024], sC2[1024];
    __shared__ unsigned short sOutI[1024];

    const int bh = blockIdx.x, sg = blockIdx.y;
    const int b = bh >> 2, head = bh & 3;
    const int tid = threadIdx.x, lane = tid & 31, wid = tid >> 5;
    const int jbase = sg * 256;

    sE1[tid]   = gE1[bh * 1024 + jbase + tid];
    sE2[tid]   = gE2[bh * 1024 + jbase + tid];
    sPerm[tid] = gPerm[bh * 1024 + jbase + tid];
    sBkt[tid]  = gBkt[bh * 1026 + jbase + tid];
    if (tid == 0) sBkt[256] = gBkt[bh * 1026 + jbase + 256];
    __syncthreads();

    // stage h rows in perm order (coalesced)
    const float* hhead = gH + (size_t)(b * 1024) * 128 + head * 32;
    for (int g = tid; g < 8192; g += 256) {
        int li = g >> 5, c = g & 31;
        sHr[li * 32 + c] = hhead[(size_t)sPerm[li] * 128 + c];
    }
    // stage queries for this block's buckets
    const int q0   = sBkt[0];
    const int qEnd = (sg == 3) ? 1024 : sBkt[256];
    for (int t = tid; t < qEnd - q0; t += 256) {
        sC1[t]   = gQC1[bh * 1024 + q0 + t];
        sC2[t]   = gQC2[bh * 1024 + q0 + t];
        sOutI[t] = gQOut[bh * 1024 + q0 + t];
    }
    __syncthreads();

    // offsets + grand total from segment totals
    const int seg = sg * 8 + wid;
    float tv1 = 0.f, off1 = 0.f, off2 = 0.f;
#pragma unroll
    for (int t = 0; t < 32; t++) {
        float a  = gTot[((bh * 32 + t) * 2 + 0) * 32 + lane];
        float b2 = gTot[((bh * 32 + t) * 2 + 1) * 32 + lane];
        tv1 += a;
        if (t < seg) { off1 += a; off2 += b2; }
    }

    float acc1 = off1, acc2 = off2;
    const int l0 = wid * 32;
    int qp = sBkt[l0];
    float* ob = out + (size_t)(b * 1024) * 128 + head * 32 + lane;

    for (int jj = 0; jj < 32; jj++) {
        int qe = sBkt[l0 + jj + 1];
        while (qp < qe) {                       // emit bucket t = jbase + l0 + jj
            int   qq = qp - q0;
            float c1 = sC1[qq], c2 = sC2[qq];
            int   i  = sOutI[qq];
            ob[(size_t)i * 128] = fmaf(c1, tv1 - acc1, c2 * acc2);
            qp++;
        }
        float hv = sHr[(l0 + jj) * 32 + lane];
        acc1 = fmaf(sE1[l0 + jj], hv, acc1);
        acc2 = fmaf(sE2[l0 + jj], hv, acc2);
    }
    if (seg == 31) {                            // bucket 1024 (k == 1024)
        while (qp < 1024) {
            int   qq = qp - q0;
            float c1 = sC1[qq], c2 = sC2[qq];
            int   i  = sOutI[qq];
            ob[(size_t)i * 128] = fmaf(c1, tv1 - acc1, c2 * acc2);
            qp++;
        }
    }
}

// ---------------------------------------------------------------------------
extern "C" void kernel_launch(void* const* d_in, const int* in_sizes, int n_in,
                              void* d_out, int out_size) {
    const float* x     = (const float*)d_in[0];
    const float* W     = (const float*)d_in[1];
    const float* a_src = (const float*)d_in[2];
    const float* a_dst = (const float*)d_in[3];
    float*       out   = (float*)d_out;

    static int smem_set = 0;
    if (!smem_set) {
        cudaFuncSetAttribute(prep_kernel, cudaFuncAttributeMaxDynamicSharedMemorySize,
                             (int)sizeof(PrepSmem));
        smem_set = 1;
    }

    gemm_kernel<<<dim3(B_ * N_ / 64, 2), 256>>>(x, W);
    prep_kernel<<<BH_, 1024, sizeof(PrepSmem)>>>(a_src, a_dst);
    pvq_kernel<<<dim3(BH_, 4), 256>>>(out);
}

// round 6
// speedup vs baseline: 1.1925x; 1.1925x over previous
#include <cuda_runtime.h>

#define B_    8
#define N_    1024
#define H_    4
#define NEG   0.2f
#define BH_   32

// Scratch (__device__ globals; no allocation allowed)
__device__ float gH[B_ * N_ * 128];            // projected features (4 MB)

// ---------------------------------------------------------------------------
// Kernel 1: h = x @ W   (8192x128 @ 128x128, fp32). 64x64 tile, 4x4/thread.
// ---------------------------------------------------------------------------
__global__ __launch_bounds__(256) void gemm_kernel(const float* __restrict__ A,
                                                   const float* __restrict__ W) {
    __shared__ float As[16][64];
    __shared__ float Bs[16][64];
    const int bm = blockIdx.x * 64, bn = blockIdx.y * 64;
    const int tid = threadIdx.x, tr = tid >> 4, tc = tid & 15;

    float acc[4][4];
#pragma unroll
    for (int i = 0; i < 4; i++)
#pragma unroll
        for (int j = 0; j < 4; j++) acc[i][j] = 0.f;

    for (int k0 = 0; k0 < 128; k0 += 16) {
#pragma unroll 4
        for (int i = tid; i < 1024; i += 256) {
            int m = i >> 4, kk = i & 15;
            As[kk][m] = A[(bm + m) * 128 + k0 + kk];
        }
#pragma unroll 4
        for (int i = tid; i < 1024; i += 256) {
            int kk = i >> 6, n = i & 63;
            Bs[kk][n] = W[(k0 + kk) * 128 + bn + n];
        }
        __syncthreads();
#pragma unroll
        for (int kk = 0; kk < 16; kk++) {
            float a[4], b[4];
#pragma unroll
            for (int i = 0; i < 4; i++) a[i] = As[kk][tr * 4 + i];
#pragma unroll
            for (int j = 0; j < 4; j++) b[j] = Bs[kk][tc * 4 + j];
#pragma unroll
            for (int i = 0; i < 4; i++)
#pragma unroll
                for (int j = 0; j < 4; j++) acc[i][j] = fmaf(a[i], b[j], acc[i][j]);
        }
        __syncthreads();
    }
#pragma unroll
    for (int i = 0; i < 4; i++)
        *reinterpret_cast<float4*>(&gH[(bm + tr * 4 + i) * 128 + bn + tc * 4]) =
            make_float4(acc[i][0], acc[i][1], acc[i][2], acc[i][3]);
}

// ---------------------------------------------------------------------------
// Mega kernel: one block per (b,h), 1024 threads. Everything in smem:
// dots -> sort -> exps -> scans -> search+coeffs -> bucket-sort queries ->
// segment totals -> merge-emit (prefix accumulate + emit queries inline).
// No global intermediates beyond gH; no threadfence.
// ---------------------------------------------------------------------------
struct MegaSmem {
    float          hL[1024 * 33];    // head slice, stride-33 (132 KB)
    float          dv[1024];
    float          e1[1024], e2[1024];
    float          pe1[1024], pe2[1024];
    float          qc1[1024], qc2[1024];   // per-query coeffs, bucket order
    unsigned short qout[1024];             // original query index, bucket order
    unsigned short pm[1024];
    float          t1s[32][32], t2s[32][32];
    float          wsum[32];
    int            wsumI[32];
    float          asr[32], ads[32];
    int            cnt[1025];
    int            starts[1026];
};

__device__ __forceinline__ void shfl_pass(float& v, int& idx, int j, int k, int tid) {
    float pv = __shfl_xor_sync(0xFFFFFFFFu, v, j);
    int   pi = __shfl_xor_sync(0xFFFFFFFFu, idx, j);
    bool  up   = ((tid & k) == 0);
    bool  iLow = ((tid & j) == 0);
    float lo = iLow ? v : pv, hi = iLow ? pv : v;
    bool  sw = up ? (lo > hi) : (lo < hi);
    if (sw) { v = pv; idx = pi; }
}

__global__ __launch_bounds__(1024) void mega_kernel(const float* __restrict__ a_src,
                                                    const float* __restrict__ a_dst,
                                                    float* __restrict__ out) {
    extern __shared__ char smem_raw[];
    MegaSmem& S = *reinterpret_cast<MegaSmem*>(smem_raw);

    const int bh = blockIdx.x, b = bh >> 2, head = bh & 3;
    const int tid = threadIdx.x, lane = tid & 31, wid = tid >> 5;
    const float* hbase = gH + (size_t)(b * 1024) * 128 + head * 32;

    if (tid < 32) { S.asr[tid] = a_src[head * 32 + tid]; S.ads[tid] = a_dst[head * 32 + tid]; }

    // --- stage head slice (coalesced float4 reads) ---
    for (int g = tid; g < 8192; g += 1024) {
        int r = g >> 3, c4 = g & 7;
        float4 v = reinterpret_cast<const float4*>(hbase + (size_t)r * 128)[c4];
        int base = r * 33 + c4 * 4;
        S.hL[base + 0] = v.x; S.hL[base + 1] = v.y;
        S.hL[base + 2] = v.z; S.hL[base + 3] = v.w;
    }
    __syncthreads();

    // --- dots ---
    float v, s;
    {
        float accd = 0.f, accs = 0.f;
#pragma unroll
        for (int c = 0; c < 32; c++) {
            float hv = S.hL[tid * 33 + c];
            accd = fmaf(hv, S.ads[c], accd);
            accs = fmaf(hv, S.asr[c], accs);
        }
        v = accd; s = accs;
    }
    int idx = tid;

    // --- bitonic sort: k=2..32 in registers (shfl) ---
#pragma unroll
    for (int k = 2; k <= 32; k <<= 1)
#pragma unroll
        for (int j = k >> 1; j >= 1; j >>= 1) shfl_pass(v, idx, j, k, tid);
    S.dv[tid] = v; S.pm[tid] = (unsigned short)idx;
    __syncthreads();

    // --- k=64..1024: cross-warp smem passes + shfl tails ---
    for (int k = 64; k <= 1024; k <<= 1) {
        for (int j = k >> 1; j >= 32; j >>= 1) {
            float          v0 = S.dv[tid];
            unsigned short i0 = S.pm[tid];
            float          pv = S.dv[tid ^ j];
            unsigned short pi = S.pm[tid ^ j];
            bool  up   = ((tid & k) == 0);
            bool  iLow = ((tid & j) == 0);
            float lo = iLow ? v0 : pv, hi = iLow ? pv : v0;
            bool  sw = up ? (lo > hi) : (lo < hi);
            __syncthreads();
            S.dv[tid] = sw ? pv : v0;
            S.pm[tid] = sw ? pi : i0;
            __syncthreads();
        }
        v = S.dv[tid]; idx = S.pm[tid];
#pragma unroll
        for (int j = 16; j >= 1; j >>= 1) shfl_pass(v, idx, j, k, tid);
        S.dv[tid] = v; S.pm[tid] = (unsigned short)idx;
        __syncthreads();
    }

    // --- exps (v == sorted d at tid) ---
    const float dmax = S.dv[1023];
    float x   = v - dmax;
    float e1v = __expf(x);
    float e2v = __expf(NEG * x);
    S.e1[tid] = e1v;
    S.e2[tid] = e2v;

    // --- inclusive block scans of e1, e2 ---
#pragma unroll
    for (int f = 0; f < 2; f++) {
        float sv = f ? e2v : e1v;
#pragma unroll
        for (int off = 1; off < 32; off <<= 1) {
            float n = __shfl_up_sync(0xFFFFFFFFu, sv, off);
            if (lane >= off) sv += n;
        }
        if (lane == 31) S.wsum[wid] = sv;
        __syncthreads();
        if (wid == 0) {
            float w = S.wsum[lane];
#pragma unroll
            for (int off = 1; off < 32; off <<= 1) {
                float n = __shfl_up_sync(0xFFFFFFFFu, w, off);
                if (lane >= off) w += n;
            }
            S.wsum[lane] = w;
        }
        __syncthreads();
        (f ? S.pe2 : S.pe1)[tid] = sv + (wid ? S.wsum[wid - 1] : 0.f);
        __syncthreads();
    }

    // --- binary search + per-query coefficients ---
    float c1c, c2c;
    int   kk;
    {
        const float T1 = S.pe1[1023];
        float key = -s;
        int   k   = 0;
#pragma unroll
        for (int step = 1024; step >= 1; step >>= 1) {
            int nk = k + step;
            if (nk <= 1024 && S.dv[nk - 1] < key) k = nk;
        }
        kk = k;
        float u  = s + dmax;
        float m  = fmaxf(u, NEG * u);
        float w1 = __expf(u - m);
        float w2 = __expf(NEG * u - m);
        float P1 = (k > 0) ? S.pe1[k - 1] : 0.f;
        float P2 = (k > 0) ? S.pe2[k - 1] : 0.f;
        float den = fmaf(w1, T1 - P1, w2 * P2);
        float inv = 1.f / den;
        c1c = w1 * inv;
        c2c = w2 * inv;
    }

    // --- counting sort of queries by bucket = k (0..1024) ---
    for (int i = tid; i < 1025; i += 1024) S.cnt[i] = 0;
    __syncthreads();
    atomicAdd(&S.cnt[kk], 1);
    __syncthreads();
    {
        int cv = S.cnt[tid];
#pragma unroll
        for (int off = 1; off < 32; off <<= 1) {
            int n = __shfl_up_sync(0xFFFFFFFFu, cv, off);
            if (lane >= off) cv += n;
        }
        if (lane == 31) S.wsumI[wid] = cv;
        __syncthreads();
        if (wid == 0) {
            int w = S.wsumI[lane];
#pragma unroll
            for (int off = 1; off < 32; off <<= 1) {
                int n = __shfl_up_sync(0xFFFFFFFFu, w, off);
                if (lane >= off) w += n;
            }
            S.wsumI[lane] = w;
        }
        __syncthreads();
        S.starts[tid + 1] = cv + (wid ? S.wsumI[wid - 1] : 0);
        if (tid == 0) S.starts[0] = 0;
        __syncthreads();
        if (tid == 0) S.starts[1025] = S.starts[1024] + S.cnt[1024];
        __syncthreads();
    }
    for (int i = tid; i < 1025; i += 1024) S.cnt[i] = 0;
    __syncthreads();
    {
        int pos = S.starts[kk] + atomicAdd(&S.cnt[kk], 1);
        S.qc1[pos]  = c1c;
        S.qc2[pos]  = c2c;
        S.qout[pos] = (unsigned short)tid;
    }
    __syncthreads();

    // --- per-segment vector totals (warp = seg, lane = channel) ---
    {
        const int j0 = wid * 32;
        float t1 = 0.f, t2 = 0.f;
#pragma unroll
        for (int jj = 0; jj < 32; jj++) {
            int   j  = j0 + jj;
            float hv = S.hL[S.pm[j] * 33 + lane];
            t1 = fmaf(S.e1[j], hv, t1);
            t2 = fmaf(S.e2[j], hv, t2);
        }
        S.t1s[wid][lane] = t1;
        S.t2s[wid][lane] = t2;
    }
    __syncthreads();

    // --- offsets + grand total ---
    float tv1 = 0.f, off1 = 0.f, off2 = 0.f;
#pragma unroll
    for (int t = 0; t < 32; t++) {
        float a  = S.t1s[t][lane];
        float b2 = S.t2s[t][lane];
        tv1 += a;
        if (t < wid) { off1 += a; off2 += b2; }
    }

    // --- merge-emit: accumulate prefix, emit queries of each bucket inline ---
    float acc1 = off1, acc2 = off2;
    const int l0 = wid * 32;
    int    qp = S.starts[l0];
    float* ob = out + (size_t)(b * 1024) * 128 + head * 32 + lane;

    for (int jj = 0; jj < 32; jj++) {
        int qe = S.starts[l0 + jj + 1];
        while (qp < qe) {                       // bucket k == l0 + jj
            float c1 = S.qc1[qp], c2 = S.qc2[qp];
            int   i  = S.qout[qp];
            ob[(size_t)i * 128] = fmaf(c1, tv1 - acc1, c2 * acc2);
            qp++;
        }
        float hv = S.hL[S.pm[l0 + jj] * 33 + lane];
        acc1 = fmaf(S.e1[l0 + jj], hv, acc1);
        acc2 = fmaf(S.e2[l0 + jj], hv, acc2);
    }
    if (wid == 31) {                            // bucket k == 1024
        while (qp < 1024) {
            float c1 = S.qc1[qp], c2 = S.qc2[qp];
            int   i  = S.qout[qp];
            ob[(size_t)i * 128] = fmaf(c1, tv1 - acc1, c2 * acc2);
            qp++;
        }
    }
}

// ---------------------------------------------------------------------------
extern "C" void kernel_launch(void* const* d_in, const int* in_sizes, int n_in,
                              void* d_out, int out_size) {
    const float* x     = (const float*)d_in[0];
    const float* W     = (const float*)d_in[1];
    const float* a_src = (const float*)d_in[2];
    const float* a_dst = (const float*)d_in[3];
    float*       out   = (float*)d_out;

    static int smem_set = 0;
    if (!smem_set) {
        cudaFuncSetAttribute(mega_kernel, cudaFuncAttributeMaxDynamicSharedMemorySize,
                             (int)sizeof(MegaSmem));
        smem_set = 1;
    }

    gemm_kernel<<<dim3(B_ * N_ / 64, 2), 256>>>(x, W);
    mega_kernel<<<BH_, 1024, sizeof(MegaSmem)>>>(a_src, a_dst, out);
}

// round 7
// speedup vs baseline: 1.8524x; 1.5534x over previous
#include <cuda_runtime.h>

#define B_    8
#define N_    1024
#define H_    4
#define NEG   0.2f
#define BH_   32

// Scratch (__device__ globals; no allocation allowed)
__device__ float gH[B_ * N_ * 128];            // projected features (4 MB)

// ---------------------------------------------------------------------------
// Kernel 1: h = x @ W   (8192x128 @ 128x128, fp32). 64x64 tile, 4x4/thread.
// ---------------------------------------------------------------------------
__global__ __launch_bounds__(256) void gemm_kernel(const float* __restrict__ A,
                                                   const float* __restrict__ W) {
    __shared__ float As[16][64];
    __shared__ float Bs[16][64];
    const int bm = blockIdx.x * 64, bn = blockIdx.y * 64;
    const int tid = threadIdx.x, tr = tid >> 4, tc = tid & 15;

    float acc[4][4];
#pragma unroll
    for (int i = 0; i < 4; i++)
#pragma unroll
        for (int j = 0; j < 4; j++) acc[i][j] = 0.f;

    for (int k0 = 0; k0 < 128; k0 += 16) {
#pragma unroll 4
        for (int i = tid; i < 1024; i += 256) {
            int m = i >> 4, kk = i & 15;
            As[kk][m] = A[(bm + m) * 128 + k0 + kk];
        }
#pragma unroll 4
        for (int i = tid; i < 1024; i += 256) {
            int kk = i >> 6, n = i & 63;
            Bs[kk][n] = W[(k0 + kk) * 128 + bn + n];
        }
        __syncthreads();
#pragma unroll
        for (int kk = 0; kk < 16; kk++) {
            float a[4], b[4];
#pragma unroll
            for (int i = 0; i < 4; i++) a[i] = As[kk][tr * 4 + i];
#pragma unroll
            for (int j = 0; j < 4; j++) b[j] = Bs[kk][tc * 4 + j];
#pragma unroll
            for (int i = 0; i < 4; i++)
#pragma unroll
                for (int j = 0; j < 4; j++) acc[i][j] = fmaf(a[i], b[j], acc[i][j]);
        }
        __syncthreads();
    }
#pragma unroll
    for (int i = 0; i < 4; i++)
        *reinterpret_cast<float4*>(&gH[(bm + tr * 4 + i) * 128 + bn + tc * 4]) =
            make_float4(acc[i][0], acc[i][1], acc[i][2], acc[i][3]);
}

// ---------------------------------------------------------------------------
// Mega kernel: one block per (b,h), 1024 threads. All phases in smem.
// Ping-pong bitonic (1 barrier/pass), float2-fused scalar streams,
// counting-sort of queries, merge-emit. No global intermediates beyond gH.
// ---------------------------------------------------------------------------
struct MegaSmem {
    float          hL[1024 * 33];     // head slice, stride-33 (132 KB)
    float2         e[1024];           // (e1, e2), sorted order
    float2         pe[1024];          // inclusive scans of e
    float2         qc[1024];          // per-query (c1, c2), bucket order
    float2         wsum2[32];
    float          dvA[1024], dvB[1024];
    float          t1s[32][32], t2s[32][32];
    float          asr[32], ads[32];
    unsigned short pmA[1024], pmB[1024];
    unsigned short qout[1024];
    int            wsumI[32];
    int            cnt[1025];
    int            starts[1026];
};

__device__ __forceinline__ void shfl_pass(float& v, int& idx, int j, int k, int tid) {
    float pv = __shfl_xor_sync(0xFFFFFFFFu, v, j);
    int   pi = __shfl_xor_sync(0xFFFFFFFFu, idx, j);
    bool  up   = ((tid & k) == 0);
    bool  iLow = ((tid & j) == 0);
    float lo = iLow ? v : pv, hi = iLow ? pv : v;
    bool  sw = up ? (lo > hi) : (lo < hi);
    if (sw) { v = pv; idx = pi; }
}

__global__ __launch_bounds__(1024) void mega_kernel(const float* __restrict__ a_src,
                                                    const float* __restrict__ a_dst,
                                                    float* __restrict__ out) {
    extern __shared__ char smem_raw[];
    MegaSmem& S = *reinterpret_cast<MegaSmem*>(smem_raw);

    const int bh = blockIdx.x, b = bh >> 2, head = bh & 3;
    const int tid = threadIdx.x, lane = tid & 31, wid = tid >> 5;
    const float* hbase = gH + (size_t)(b * 1024) * 128 + head * 32;

    if (tid < 32) { S.asr[tid] = a_src[head * 32 + tid]; S.ads[tid] = a_dst[head * 32 + tid]; }

    // --- stage head slice (coalesced float4 reads, stride-33 smem) ---
    for (int g = tid; g < 8192; g += 1024) {
        int r = g >> 3, c4 = g & 7;
        float4 v = reinterpret_cast<const float4*>(hbase + (size_t)r * 128)[c4];
        int base = r * 33 + c4 * 4;
        S.hL[base + 0] = v.x; S.hL[base + 1] = v.y;
        S.hL[base + 2] = v.z; S.hL[base + 3] = v.w;
    }
    __syncthreads();

    // --- dots ---
    float v, s;
    {
        float accd = 0.f, accs = 0.f;
#pragma unroll
        for (int c = 0; c < 32; c++) {
            float hv = S.hL[tid * 33 + c];
            accd = fmaf(hv, S.ads[c], accd);
            accs = fmaf(hv, S.asr[c], accs);
        }
        v = accd; s = accs;
    }
    int idx = tid;

    // --- bitonic sort: k=2..32 in registers (shfl) ---
#pragma unroll
    for (int k = 2; k <= 32; k <<= 1)
#pragma unroll
        for (int j = k >> 1; j >= 1; j >>= 1) shfl_pass(v, idx, j, k, tid);

    float*          dvc = S.dvA;  float*          dvn = S.dvB;
    unsigned short* pmc = S.pmA;  unsigned short* pmn = S.pmB;
    dvc[tid] = v; pmc[tid] = (unsigned short)idx;
    __syncthreads();

    // --- k=64..1024: ping-pong cross-warp passes (1 barrier each) + shfl tails ---
    for (int k = 64; k <= 1024; k <<= 1) {
        for (int j = k >> 1; j >= 32; j >>= 1) {
            float          v0 = dvc[tid];
            unsigned short i0 = pmc[tid];
            float          pv = dvc[tid ^ j];
            unsigned short pi = pmc[tid ^ j];
            bool  up   = ((tid & k) == 0);
            bool  iLow = ((tid & j) == 0);
            float lo = iLow ? v0 : pv, hi = iLow ? pv : v0;
            bool  sw = up ? (lo > hi) : (lo < hi);
            dvn[tid] = sw ? pv : v0;
            pmn[tid] = sw ? pi : i0;
            __syncthreads();
            float* tf = dvc; dvc = dvn; dvn = tf;
            unsigned short* tp = pmc; pmc = pmn; pmn = tp;
        }
        v = dvc[tid]; idx = pmc[tid];
#pragma unroll
        for (int j = 16; j >= 1; j >>= 1) shfl_pass(v, idx, j, k, tid);
        dvc[tid] = v; pmc[tid] = (unsigned short)idx;
        __syncthreads();
    }
    const float*          dvf = dvc;   // final sorted keys
    const unsigned short* pmf = pmc;   // final permutation

    // --- exps (v == sorted d at tid) ---
    const float dmax = dvf[1023];
    float  x  = v - dmax;
    float2 ev = make_float2(__expf(x), __expf(NEG * x));
    S.e[tid] = ev;

    // --- fused inclusive block scan of (e1, e2) ---
    {
        float2 sv = ev;
#pragma unroll
        for (int off = 1; off < 32; off <<= 1) {
            float nx = __shfl_up_sync(0xFFFFFFFFu, sv.x, off);
            float ny = __shfl_up_sync(0xFFFFFFFFu, sv.y, off);
            if (lane >= off) { sv.x += nx; sv.y += ny; }
        }
        if (lane == 31) S.wsum2[wid] = sv;
        __syncthreads();
        if (wid == 0) {
            float2 w = S.wsum2[lane];
#pragma unroll
            for (int off = 1; off < 32; off <<= 1) {
                float nx = __shfl_up_sync(0xFFFFFFFFu, w.x, off);
                float ny = __shfl_up_sync(0xFFFFFFFFu, w.y, off);
                if (lane >= off) { w.x += nx; w.y += ny; }
            }
            S.wsum2[lane] = w;
        }
        __syncthreads();
        if (wid) { float2 c = S.wsum2[wid - 1]; sv.x += c.x; sv.y += c.y; }
        S.pe[tid] = sv;
        __syncthreads();
    }

    // --- binary search + per-query coefficients ---
    float c1c, c2c;
    int   kk;
    {
        const float T1 = S.pe[1023].x;
        float key = -s;
        int   k   = 0;
#pragma unroll
        for (int step = 1024; step >= 1; step >>= 1) {
            int nk = k + step;
            if (nk <= 1024 && dvf[nk - 1] < key) k = nk;
        }
        kk = k;
        float u  = s + dmax;
        float m  = fmaxf(u, NEG * u);
        float w1 = __expf(u - m);
        float w2 = __expf(NEG * u - m);
        float2 P = (k > 0) ? S.pe[k - 1] : make_float2(0.f, 0.f);
        float den = fmaf(w1, T1 - P.x, w2 * P.y);
        float inv = 1.f / den;
        c1c = w1 * inv;
        c2c = w2 * inv;
    }

    // --- counting sort of queries by bucket = k (0..1024) ---
    for (int i = tid; i < 1025; i += 1024) S.cnt[i] = 0;
    __syncthreads();
    atomicAdd(&S.cnt[kk], 1);
    __syncthreads();
    {
        int cv = S.cnt[tid];
#pragma unroll
        for (int off = 1; off < 32; off <<= 1) {
            int n = __shfl_up_sync(0xFFFFFFFFu, cv, off);
            if (lane >= off) cv += n;
        }
        if (lane == 31) S.wsumI[wid] = cv;
        __syncthreads();
        if (wid == 0) {
            int w = S.wsumI[lane];
#pragma unroll
            for (int off = 1; off < 32; off <<= 1) {
                int n = __shfl_up_sync(0xFFFFFFFFu, w, off);
                if (lane >= off) w += n;
            }
            S.wsumI[lane] = w;
        }
        __syncthreads();
        S.starts[tid + 1] = cv + (wid ? S.wsumI[wid - 1] : 0);
        if (tid == 0) S.starts[0] = 0;
        __syncthreads();
        if (tid == 0) S.starts[1025] = S.starts[1024] + S.cnt[1024];
        __syncthreads();
    }
    for (int i = tid; i < 1025; i += 1024) S.cnt[i] = 0;
    __syncthreads();
    {
        int pos = S.starts[kk] + atomicAdd(&S.cnt[kk], 1);
        S.qc[pos]   = make_float2(c1c, c2c);
        S.qout[pos] = (unsigned short)tid;
    }
    __syncthreads();

    // --- per-segment vector totals (warp = seg, lane = channel) ---
    {
        const int j0 = wid * 32;
        float t1 = 0.f, t2 = 0.f;
#pragma unroll
        for (int jj = 0; jj < 32; jj++) {
            int    j  = j0 + jj;
            float  hv = S.hL[pmf[j] * 33 + lane];
            float2 ee = S.e[j];
            t1 = fmaf(ee.x, hv, t1);
            t2 = fmaf(ee.y, hv, t2);
        }
        S.t1s[wid][lane] = t1;
        S.t2s[wid][lane] = t2;
    }
    __syncthreads();

    // --- offsets + grand total ---
    float tv1 = 0.f, off1 = 0.f, off2 = 0.f;
#pragma unroll
    for (int t = 0; t < 32; t++) {
        float a  = S.t1s[t][lane];
        float b2 = S.t2s[t][lane];
        tv1 += a;
        if (t < wid) { off1 += a; off2 += b2; }
    }

    // --- merge-emit: accumulate prefix, emit queries of each bucket inline ---
    float acc1 = off1, acc2 = off2;
    const int l0 = wid * 32;
    int    qp = S.starts[l0];
    float* ob = out + (size_t)(b * 1024) * 128 + head * 32 + lane;

    for (int jj = 0; jj < 32; jj++) {
        int qe = S.starts[l0 + jj + 1];
        while (qp < qe) {                       // bucket k == l0 + jj
            float2 cc = S.qc[qp];
            int    i  = S.qout[qp];
            ob[(size_t)i * 128] = fmaf(cc.x, tv1 - acc1, cc.y * acc2);
            qp++;
        }
        float  hv = S.hL[pmf[l0 + jj] * 33 + lane];
        float2 ee = S.e[l0 + jj];
        acc1 = fmaf(ee.x, hv, acc1);
        acc2 = fmaf(ee.y, hv, acc2);
    }
    if (wid == 31) {                            // bucket k == 1024
        while (qp < 1024) {
            float2 cc = S.qc[qp];
            int    i  = S.qout[qp];
            ob[(size_t)i * 128] = fmaf(cc.x, tv1 - acc1, cc.y * acc2);
            qp++;
        }
    }
}

// ---------------------------------------------------------------------------
extern "C" void kernel_launch(void* const* d_in, const int* in_sizes, int n_in,
                              void* d_out, int out_size) {
    const float* x     = (const float*)d_in[0];
    const float* W     = (const float*)d_in[1];
    const float* a_src = (const float*)d_in[2];
    const float* a_dst = (const float*)d_in[3];
    float*       out   = (float*)d_out;

    static int smem_set = 0;
    if (!smem_set) {
        cudaFuncSetAttribute(mega_kernel, cudaFuncAttributeMaxDynamicSharedMemorySize,
                             (int)sizeof(MegaSmem));
        smem_set = 1;
    }

    gemm_kernel<<<dim3(B_ * N_ / 64, 2), 256>>>(x, W);
    mega_kernel<<<BH_, 1024, sizeof(MegaSmem)>>>(a_src, a_dst, out);
}